// round 14
// baseline (speedup 1.0000x reference)
#include <cuda_runtime.h>
#include <cuda_bf16.h>
#include <cstdint>

// RNN_50036368998466 via warp-level HMMA (mma.sync m16n8k16 bf16).
// R14: B-image deduped to K=64 ([Whi | Wlo]); hi fragments reused for the
// Ah@Bhi and Al@Bhi k-steps (LDSM 42->28 x4/warp). o1 epilogue transpose uses
// a [16][132] column-major smem layout: writes hit banks (8t+g)%32 (distinct),
// reads are lane-consecutive -> conflict-free.

typedef uint32_t u32;

__device__ __align__(16) float g_wbuf[240];
__constant__ __align__(16) float cbuf[240];
// cbuf: [0..31] wih, [32..63] bsum, [64..79] b1, [80..207] W2, [208..215] b2,
//       [216..223] W3, [224] b3
// B image (bf16, rows 128B): [0,4096)B Whh 32rows x K64; [4096+2048*t)B W1_t 16rows x K64
__device__ __align__(16) __nv_bfloat16 g_bimg[5120];   // 10240 bytes

__device__ __forceinline__ float tanh_fast(float x) {
    float t; asm("tanh.approx.f32 %0, %1;" : "=f"(t) : "f"(x));
    return t;
}
__device__ __forceinline__ u32 pack_bf16(float a, float b) {  // lo=a, hi=b
    u32 r; asm("cvt.rn.bf16x2.f32 %0, %1, %2;" : "=r"(r) : "f"(b), "f"(a));
    return r;
}
__device__ __forceinline__ void split4(float v0, float v1, float v2, float v3,
                                       u32& h01, u32& h23, u32& l01, u32& l23) {
    h01 = pack_bf16(v0, v1); h23 = pack_bf16(v2, v3);
    float f0 = __uint_as_float(h01 << 16), f1 = __uint_as_float(h01 & 0xffff0000u);
    float f2 = __uint_as_float(h23 << 16), f3 = __uint_as_float(h23 & 0xffff0000u);
    l01 = pack_bf16(v0 - f0, v1 - f1); l23 = pack_bf16(v2 - f2, v3 - f3);
}
__device__ __forceinline__ u32 smem_u32(const void* p) {
    u32 a;
    asm("{ .reg .u64 t; cvta.to.shared.u64 t, %1; cvt.u32.u64 %0, t; }" : "=r"(a) : "l"(p));
    return a;
}
__device__ __forceinline__ void ldsm4(u32 a, u32& r0, u32& r1, u32& r2, u32& r3) {
    asm volatile("ldmatrix.sync.aligned.m8n8.x4.shared.b16 {%0,%1,%2,%3}, [%4];"
                 : "=r"(r0), "=r"(r1), "=r"(r2), "=r"(r3) : "r"(a));
}
__device__ __forceinline__ void mma16816(float* c, const u32* a, u32 b0, u32 b1) {
    asm volatile("mma.sync.aligned.m16n8k16.row.col.f32.bf16.bf16.f32 "
                 "{%0,%1,%2,%3}, {%4,%5,%6,%7}, {%8,%9}, {%0,%1,%2,%3};"
                 : "+f"(c[0]), "+f"(c[1]), "+f"(c[2]), "+f"(c[3])
                 : "r"(a[0]), "r"(a[1]), "r"(a[2]), "r"(a[3]), "r"(b0), "r"(b1));
}

// ---------------- pack kernel ----------------
__global__ __launch_bounds__(128)
void pack_weights(const float* __restrict__ W_ih, const float* __restrict__ W_hh,
                  const float* __restrict__ b_ih, const float* __restrict__ b_hh,
                  const float* __restrict__ W1,   const float* __restrict__ b1,
                  const float* __restrict__ W2,   const float* __restrict__ b2,
                  const float* __restrict__ W3,   const float* __restrict__ b3) {
    const int tid = threadIdx.x;
    if (tid < 32) { g_wbuf[tid] = W_ih[tid]; g_wbuf[32 + tid] = b_ih[tid] + b_hh[tid]; }
    if (tid < 16) g_wbuf[64 + tid] = b1[tid];
    g_wbuf[80 + tid] = W2[tid];
    if (tid < 8) { g_wbuf[208 + tid] = b2[tid]; g_wbuf[216 + tid] = W3[tid]; }
    if (tid == 0) g_wbuf[224] = b3[0];

    // Whh-B [n][k], k<32 -> hi(Whh[n][k]); k in 32..63 -> lo(Whh[n][k-32])
    for (int i = tid; i < 32 * 64; i += 128) {
        int n = i >> 6, k = i & 63;
        float w = W_hh[n * 32 + (k & 31)];
        __nv_bfloat16 hi = __float2bfloat16(w);
        g_bimg[i] = (k < 32) ? hi : __float2bfloat16(w - __bfloat162float(hi));
    }
    // W1-B_t [n][k]: base value W1[n][32t + (k&31)], hi | lo
    for (int i = tid; i < 3 * 16 * 64; i += 128) {
        int t = i >> 10, r = i & 1023, n = r >> 6, k = r & 63;
        float w = W1[n * 96 + 32 * t + (k & 31)];
        __nv_bfloat16 hi = __float2bfloat16(w);
        g_bimg[2048 + i] = (k < 32) ? hi : __float2bfloat16(w - __bfloat162float(hi));
    }
}

// ---------------- main kernel ----------------
__global__ __launch_bounds__(128, 3)
void rnn_hmma(const float* __restrict__ x, float* __restrict__ out) {
    __shared__ __align__(16) __nv_bfloat16 sB[5120];   // 10240 B
    __shared__ float sWih[32], sBsum[32];
    __shared__ float sX[3][128];
    __shared__ __align__(16) float sO1[16 * 132];      // [col][row+pad4]

    const int tid = threadIdx.x;
    {   // stage B (640 float4)
        const float4* src = reinterpret_cast<const float4*>(g_bimg);
        float4* dst = reinterpret_cast<float4*>(sB);
#pragma unroll
        for (int i = 0; i < 5; i++) dst[tid + i * 128] = src[tid + i * 128];
    }
    if (tid < 32) { sWih[tid] = cbuf[tid]; sBsum[tid] = cbuf[32 + tid]; }
    {
        const float* xe = x + 3 * (size_t)(blockIdx.x * 128 + tid);
        sX[0][tid] = xe[0]; sX[1][tid] = xe[1]; sX[2][tid] = xe[2];
    }
    __syncthreads();

    const int lane = tid & 31, w = tid >> 5;
    const int g = lane >> 2, t = lane & 3;

    float wihc[8], bsc[8];
#pragma unroll
    for (int nt = 0; nt < 4; nt++) {
        wihc[2 * nt]     = sWih[8 * nt + 2 * t];
        wihc[2 * nt + 1] = sWih[8 * nt + 2 * t + 1];
        bsc[2 * nt]      = sBsum[8 * nt + 2 * t];
        bsc[2 * nt + 1]  = sBsum[8 * nt + 2 * t + 1];
    }
    const int rr = 32 * w + g;
    float xr[3][4];
#pragma unroll
    for (int s = 0; s < 3; s++) {
        xr[s][0] = sX[s][rr];      xr[s][1] = sX[s][rr + 8];
        xr[s][2] = sX[s][rr + 16]; xr[s][3] = sX[s][rr + 24];
    }

    const u32 sBaddr = smem_u32(sB);
    // ldmatrix lane offset for 128B rows: matrices (n0-7,klo),(n0-7,khi),(n8-15,klo),(n8-15,khi)
    const u32 boff = (u32)((((lane >> 4) & 1) * 8 + (lane & 7)) * 128 + ((lane >> 3) & 1) * 16);

    u32 Ah[2][8], Al[2][8];
    float O1[2][2][4];
    float Cr[2][4][4];
#pragma unroll
    for (int a = 0; a < 2; a++)
#pragma unroll
        for (int b = 0; b < 2; b++)
#pragma unroll
            for (int c = 0; c < 4; c++) O1[a][b][c] = 0.f;

    // ---- step 1: h1 in fragment positions ----
#pragma unroll
    for (int mt = 0; mt < 2; mt++) {
        float xq0 = xr[0][2 * mt], xq1 = xr[0][2 * mt + 1];
#pragma unroll
        for (int nt = 0; nt < 4; nt++) {
            float v0 = tanh_fast(fmaf(xq0, wihc[2 * nt],     bsc[2 * nt]));
            float v1 = tanh_fast(fmaf(xq0, wihc[2 * nt + 1], bsc[2 * nt + 1]));
            float v2 = tanh_fast(fmaf(xq1, wihc[2 * nt],     bsc[2 * nt]));
            float v3 = tanh_fast(fmaf(xq1, wihc[2 * nt + 1], bsc[2 * nt + 1]));
            int base = (nt >> 1) * 4 + (nt & 1) * 2;
            split4(v0, v1, v2, v3, Ah[mt][base], Ah[mt][base + 1], Al[mt][base], Al[mt][base + 1]);
        }
    }

// recurrence GEMM: per pair load H0,H1 (hi kt0/kt1) -> Ah,Al products; L0,L1 (lo) -> Ah products
#define REC_GEMM() do { \
    _Pragma("unroll") \
    for (int mt = 0; mt < 2; mt++) \
        _Pragma("unroll") \
        for (int nt = 0; nt < 4; nt++) \
            _Pragma("unroll") \
            for (int j = 0; j < 4; j++) Cr[mt][nt][j] = 0.f; \
    _Pragma("unroll") \
    for (int pair = 0; pair < 2; pair++) { \
        const u32 pb = sBaddr + (u32)(pair * 2048) + boff; \
        u32 h0a, h0b, h0c, h0d, h1a, h1b, h1c, h1d; \
        ldsm4(pb + 0,  h0a, h0b, h0c, h0d); \
        ldsm4(pb + 32, h1a, h1b, h1c, h1d); \
        _Pragma("unroll") \
        for (int mt = 0; mt < 2; mt++) { \
            mma16816(Cr[mt][2 * pair],     &Ah[mt][0], h0a, h0b); \
            mma16816(Cr[mt][2 * pair + 1], &Ah[mt][0], h0c, h0d); \
            mma16816(Cr[mt][2 * pair],     &Ah[mt][4], h1a, h1b); \
            mma16816(Cr[mt][2 * pair + 1], &Ah[mt][4], h1c, h1d); \
            mma16816(Cr[mt][2 * pair],     &Al[mt][0], h0a, h0b); \
            mma16816(Cr[mt][2 * pair + 1], &Al[mt][0], h0c, h0d); \
            mma16816(Cr[mt][2 * pair],     &Al[mt][4], h1a, h1b); \
            mma16816(Cr[mt][2 * pair + 1], &Al[mt][4], h1c, h1d); \
        } \
        ldsm4(pb + 64, h0a, h0b, h0c, h0d); \
        ldsm4(pb + 96, h1a, h1b, h1c, h1d); \
        _Pragma("unroll") \
        for (int mt = 0; mt < 2; mt++) { \
            mma16816(Cr[mt][2 * pair],     &Ah[mt][0], h0a, h0b); \
            mma16816(Cr[mt][2 * pair + 1], &Ah[mt][0], h0c, h0d); \
            mma16816(Cr[mt][2 * pair],     &Ah[mt][4], h1a, h1b); \
            mma16816(Cr[mt][2 * pair + 1], &Ah[mt][4], h1c, h1d); \
        } \
    } \
} while (0)

#define RELU_A() do { \
    _Pragma("unroll") \
    for (int mt = 0; mt < 2; mt++) \
        _Pragma("unroll") \
        for (int i = 0; i < 8; i++) { \
            u32 s = Ah[mt][i]; \
            u32 m = ((s >> 15) & 0x10001u) * 0xffffu; \
            Ah[mt][i] = s & ~m; \
            Al[mt][i] = Al[mt][i] & ~m; \
        } \
} while (0)

#define FC1_GEMM(step) do { \
    const u32 fb = sBaddr + (u32)(4096 + 2048 * (step)) + boff; \
    u32 h0a, h0b, h0c, h0d, h1a, h1b, h1c, h1d; \
    ldsm4(fb + 0,  h0a, h0b, h0c, h0d); \
    ldsm4(fb + 32, h1a, h1b, h1c, h1d); \
    _Pragma("unroll") \
    for (int mt = 0; mt < 2; mt++) { \
        mma16816(O1[mt][0], &Ah[mt][0], h0a, h0b); \
        mma16816(O1[mt][1], &Ah[mt][0], h0c, h0d); \
        mma16816(O1[mt][0], &Ah[mt][4], h1a, h1b); \
        mma16816(O1[mt][1], &Ah[mt][4], h1c, h1d); \
        mma16816(O1[mt][0], &Al[mt][0], h0a, h0b); \
        mma16816(O1[mt][1], &Al[mt][0], h0c, h0d); \
        mma16816(O1[mt][0], &Al[mt][4], h1a, h1b); \
        mma16816(O1[mt][1], &Al[mt][4], h1c, h1d); \
    } \
    ldsm4(fb + 64, h0a, h0b, h0c, h0d); \
    ldsm4(fb + 96, h1a, h1b, h1c, h1d); \
    _Pragma("unroll") \
    for (int mt = 0; mt < 2; mt++) { \
        mma16816(O1[mt][0], &Ah[mt][0], h0a, h0b); \
        mma16816(O1[mt][1], &Ah[mt][0], h0c, h0d); \
        mma16816(O1[mt][0], &Ah[mt][4], h1a, h1b); \
        mma16816(O1[mt][1], &Ah[mt][4], h1c, h1d); \
    } \
} while (0)

#define CONV(sidx) do { \
    _Pragma("unroll") \
    for (int mt = 0; mt < 2; mt++) { \
        float xq0 = xr[sidx][2 * mt], xq1 = xr[sidx][2 * mt + 1]; \
        _Pragma("unroll") \
        for (int nt = 0; nt < 4; nt++) { \
            float v0 = tanh_fast(Cr[mt][nt][0] + fmaf(xq0, wihc[2 * nt],     bsc[2 * nt])); \
            float v1 = tanh_fast(Cr[mt][nt][1] + fmaf(xq0, wihc[2 * nt + 1], bsc[2 * nt + 1])); \
            float v2 = tanh_fast(Cr[mt][nt][2] + fmaf(xq1, wihc[2 * nt],     bsc[2 * nt])); \
            float v3 = tanh_fast(Cr[mt][nt][3] + fmaf(xq1, wihc[2 * nt + 1], bsc[2 * nt + 1])); \
            int base = (nt >> 1) * 4 + (nt & 1) * 2; \
            split4(v0, v1, v2, v3, Ah[mt][base], Ah[mt][base + 1], Al[mt][base], Al[mt][base + 1]); \
        } \
    } \
} while (0)

    REC_GEMM();
    RELU_A();
    FC1_GEMM(0);

    CONV(1);
    REC_GEMM();
    RELU_A();
    FC1_GEMM(1);

    // step 3: relu(tanh(...)) directly
#pragma unroll
    for (int mt = 0; mt < 2; mt++) {
        float xq0 = xr[2][2 * mt], xq1 = xr[2][2 * mt + 1];
#pragma unroll
        for (int nt = 0; nt < 4; nt++) {
            float v0 = fmaxf(tanh_fast(Cr[mt][nt][0] + fmaf(xq0, wihc[2 * nt],     bsc[2 * nt])), 0.f);
            float v1 = fmaxf(tanh_fast(Cr[mt][nt][1] + fmaf(xq0, wihc[2 * nt + 1], bsc[2 * nt + 1])), 0.f);
            float v2 = fmaxf(tanh_fast(Cr[mt][nt][2] + fmaf(xq1, wihc[2 * nt],     bsc[2 * nt])), 0.f);
            float v3 = fmaxf(tanh_fast(Cr[mt][nt][3] + fmaf(xq1, wihc[2 * nt + 1], bsc[2 * nt + 1])), 0.f);
            int base = (nt >> 1) * 4 + (nt & 1) * 2;
            split4(v0, v1, v2, v3, Ah[mt][base], Ah[mt][base + 1], Al[mt][base], Al[mt][base + 1]);
        }
    }
    FC1_GEMM(2);

    // ---- epilogue: conflict-free transposed store [col][row], then scalar fc2/fc3 ----
#pragma unroll
    for (int mt = 0; mt < 2; mt++)
#pragma unroll
        for (int nt = 0; nt < 2; nt++)
#pragma unroll
            for (int h = 0; h < 2; h++)
#pragma unroll
                for (int j = 0; j < 2; j++)
                    sO1[(8 * nt + 2 * t + j) * 132 + 32 * w + 16 * mt + 8 * h + g]
                        = O1[mt][nt][2 * h + j];
    __syncwarp();

    float o1f[16];
#pragma unroll
    for (int i = 0; i < 16; i++)
        o1f[i] = sO1[i * 132 + tid] + cbuf[64 + i];

    float acc = cbuf[224];
#pragma unroll
    for (int i = 0; i < 8; i++) {
        float s = cbuf[208 + i];
#pragma unroll
        for (int k = 0; k < 16; k++)
            s = fmaf(o1f[k], cbuf[80 + i * 16 + k], s);
        acc = fmaf(fmaxf(s, 0.0f), cbuf[216 + i], acc);
    }
    out[blockIdx.x * 128 + tid] = acc;
}

extern "C" void kernel_launch(void* const* d_in, const int* in_sizes, int n_in,
                              void* d_out, int out_size) {
    const float* x    = (const float*)d_in[0];
    const float* W_ih = (const float*)d_in[1];
    const float* W_hh = (const float*)d_in[2];
    const float* b_ih = (const float*)d_in[3];
    const float* b_hh = (const float*)d_in[4];
    const float* W1   = (const float*)d_in[5];
    const float* b1   = (const float*)d_in[6];
    const float* W2   = (const float*)d_in[7];
    const float* b2   = (const float*)d_in[8];
    const float* W3   = (const float*)d_in[9];
    const float* b3   = (const float*)d_in[10];
    float* out = (float*)d_out;

    const int B = in_sizes[0] / 3;   // 1048576 = 8192 * 128 exactly

    pack_weights<<<1, 128>>>(W_ih, W_hh, b_ih, b_hh, W1, b1, W2, b2, W3, b3);

    void* wbuf_dev = nullptr;
    cudaGetSymbolAddress(&wbuf_dev, g_wbuf);
    cudaMemcpyToSymbolAsync(cbuf, wbuf_dev, 240 * sizeof(float), 0,
                            cudaMemcpyDeviceToDevice, 0);

    rnn_hmma<<<B / 128, 128>>>(x, out);
}